// round 8
// baseline (speedup 1.0000x reference)
#include <cuda_runtime.h>
#include <cstdint>

#define IMH 256
#define IMW 256

// 402 MB scratch for hidden = conv1x1(x) + b_hidden, NCHW [4][384][256][256]
__device__ float g_hidden[4 * 384 * 256 * 256];

// ======================= K1: 1x1 conv, whole image, no halo =======================
// grid (512, 4): 512 strips of 128 contiguous pixels per batch. 1024 threads.
// warp = 4 pixels, lane = 4 channels of the 128-channel pass (3 passes).
#define K1_SMEM (64 * 128 + 64 * 132)   // xs + ws = 16640 floats

extern __shared__ float smem[];

__global__ __launch_bounds__(1024, 1)
void k1_conv1x1(const float* __restrict__ x,
                const float* __restrict__ w_hidden,
                const float* __restrict__ b_hidden)
{
    float* xs = smem;              // [64][128]
    float* ws = smem + 64 * 128;   // [64][132]

    const int t   = threadIdx.x;
    const int b   = blockIdx.y;
    const int px0 = blockIdx.x * 128;
    const int w   = t >> 5;        // warp: pixels w*4..w*4+3
    const int l   = t & 31;        // lane: channels l*4..l*4+3

    // stage x strip: xs[c][p] (coalesced)
    for (int idx = t; idx < 64 * 128; idx += 1024) {
        int c = idx >> 7, p = idx & 127;
        xs[idx] = x[((size_t)(b * 64 + c) << 16) + px0 + p];
    }

    for (int pass = 0; pass < 3; ++pass) {
        const int pch = pass * 128;
        __syncthreads();
        for (int idx = t; idx < 64 * 128; idx += 1024) {
            int i = idx & 63, c = idx >> 6;
            ws[i * 132 + c] = w_hidden[(pch + c) * 64 + i];
        }
        __syncthreads();

        float acc[4][4];
        #pragma unroll
        for (int j = 0; j < 4; ++j) {
            float bv = __ldg(&b_hidden[pch + l * 4 + j]);
            acc[j][0] = bv; acc[j][1] = bv; acc[j][2] = bv; acc[j][3] = bv;
        }
        const float* xsp = xs + w * 4;
        const float* wsp = ws + l * 4;
        #pragma unroll 4
        for (int i = 0; i < 64; ++i) {
            float4 xv = *(const float4*)(xsp + i * 128);
            float4 wv = *(const float4*)(wsp + i * 132);
            acc[0][0] += wv.x * xv.x; acc[0][1] += wv.x * xv.y;
            acc[0][2] += wv.x * xv.z; acc[0][3] += wv.x * xv.w;
            acc[1][0] += wv.y * xv.x; acc[1][1] += wv.y * xv.y;
            acc[1][2] += wv.y * xv.z; acc[1][3] += wv.y * xv.w;
            acc[2][0] += wv.z * xv.x; acc[2][1] += wv.z * xv.y;
            acc[2][2] += wv.z * xv.z; acc[2][3] += wv.z * xv.w;
            acc[3][0] += wv.w * xv.x; acc[3][1] += wv.w * xv.y;
            acc[3][2] += wv.w * xv.z; acc[3][3] += wv.w * xv.w;
        }

        #pragma unroll
        for (int j = 0; j < 4; ++j) {
            int c = pch + l * 4 + j;
            float4 hv = make_float4(acc[j][0], acc[j][1], acc[j][2], acc[j][3]);
            *(float4*)(g_hidden + ((size_t)(b * 384 + c) << 16) + px0 + w * 4) = hv;
        }
    }
}

// ======================= K2: dw conv + circ-conv + LN + proj =======================
// grid (32, 32, 4): one 8x8 patch per block. 1024 threads.
// smem (floats):
#define OFF_HS   0          // hs [128][120] = 15360; wpT[128][68] overlays after passes
#define OFF_WPT  0
#define OFF_Q    15360      // [128][68]
#define OFF_K    24064      // [128][68]
#define OFF_V    32768      // [128][68]
#define OFF_PS   41472      // [16][66]
#define OFF_PQ   42528      // [16][66]
#define OFF_MEAN 43584      // [64]
#define OFF_RSTD 43648      // [64]
#define K2_SMEM  43712      // 174848 bytes

__global__ __launch_bounds__(1024, 1)
void k2_rest(const float* __restrict__ w_dw,
             const float* __restrict__ b_dw,
             const float* __restrict__ w_proj,
             const float* __restrict__ b_proj,
             const float* __restrict__ ln_w,
             const float* __restrict__ ln_b,
             float* __restrict__ out)
{
    float* hs   = smem + OFF_HS;
    float* wpT  = smem + OFF_WPT;
    float* qsm  = smem + OFF_Q;
    float* ksm  = smem + OFF_K;
    float* vsm  = smem + OFF_V;
    float* ps   = smem + OFF_PS;
    float* pq   = smem + OFF_PQ;
    float* mean_s = smem + OFF_MEAN;
    float* rstd_s = smem + OFF_RSTD;

    const int t  = threadIdx.x;
    const int bx = blockIdx.x;
    const int by = blockIdx.y;
    const int bb = blockIdx.z;
    const int gx0 = bx * 8 - 1;
    const int gy0 = by * 8 - 1;

    const int c   = t >> 3;       // 0..127 (dw / B / LN-apply channel)
    const int row = t & 7;        // 0..7
    const int p8  = t & 63;
    const int i8  = p8 >> 3;
    const int j8  = p8 & 7;
    const int clg = t >> 6;       // 0..15

    // ---- 3 passes: stage hidden tile (zero halo) + depthwise 3x3 ----
    for (int pass = 0; pass < 3; ++pass) {
        const int pch = pass * 128;
        __syncthreads();   // hs free (prev dw done)
        for (int idx = t; idx < 128 * 128; idx += 1024) {
            int cc = idx >> 7, tp = idx & 127;
            if (tp < 100) {
                int ty = tp / 10, tx = tp - ty * 10;
                int gy = gy0 + ty, gx = gx0 + tx;
                float v = 0.f;
                if ((unsigned)gy < IMH && (unsigned)gx < IMW)
                    v = g_hidden[((size_t)(bb * 384 + pch + cc) << 16) + (gy << 8) + gx];
                hs[cc * 120 + ty * 12 + tx] = v;
            }
        }
        __syncthreads();

        float* dst = (pass == 0) ? qsm : (pass == 1) ? ksm : vsm;
        float wd9[9];
        #pragma unroll
        for (int tap = 0; tap < 9; ++tap) wd9[tap] = __ldg(&w_dw[(pch + c) * 9 + tap]);
        float bv = __ldg(&b_dw[pch + c]);
        float o8[8];
        #pragma unroll
        for (int j = 0; j < 8; ++j) o8[j] = bv;
        const float* hrow = hs + c * 120 + row * 12;
        #pragma unroll
        for (int dy = 0; dy < 3; ++dy) {
            float4 A0 = *(const float4*)(hrow + dy * 12);
            float4 A1 = *(const float4*)(hrow + dy * 12 + 4);
            float4 A2 = *(const float4*)(hrow + dy * 12 + 8);
            float rr[12] = {A0.x, A0.y, A0.z, A0.w, A1.x, A1.y, A1.z, A1.w,
                            A2.x, A2.y, A2.z, A2.w};
            float w0 = wd9[dy * 3], w1 = wd9[dy * 3 + 1], w2 = wd9[dy * 3 + 2];
            #pragma unroll
            for (int j = 0; j < 8; ++j)
                o8[j] += rr[j] * w0 + rr[j + 1] * w1 + rr[j + 2] * w2;
        }
        *(float4*)(dst + c * 68 + row * 8)     = make_float4(o8[0], o8[1], o8[2], o8[3]);
        *(float4*)(dst + c * 68 + row * 8 + 4) = make_float4(o8[4], o8[5], o8[6], o8[7]);
    }
    __syncthreads();   // dw done with hs -> overlay wpT

    // stage wpT[c][68] = w_proj[o][c]
    for (int idx = t; idx < 64 * 128; idx += 1024) {
        int cc = idx & 127, o = idx >> 7;
        wpT[cc * 68 + o] = w_proj[o * 128 + cc];
    }
    // ordered before proj by the syncs below

    // ---- Phase B: circular conv per 8x8 patch ----
    float bacc[8];
    #pragma unroll
    for (int j = 0; j < 8; ++j) bacc[j] = 0.f;
    {
        const float* qrow = qsm + c * 68;
        const float* krow = ksm + c * 68;
        #pragma unroll
        for (int a = 0; a < 8; ++a) {
            float4 qa = *(const float4*)(qrow + a * 8);
            float4 qb = *(const float4*)(qrow + a * 8 + 4);
            float qq[8] = {qa.x, qa.y, qa.z, qa.w, qb.x, qb.y, qb.z, qb.w};
            int r0 = (row - a) & 7;
            float4 k0 = *(const float4*)(krow + r0 * 8);
            float4 k1 = *(const float4*)(krow + r0 * 8 + 4);
            float kk[8] = {k0.x, k0.y, k0.z, k0.w, k1.x, k1.y, k1.z, k1.w};
            #pragma unroll
            for (int b2 = 0; b2 < 8; ++b2) {
                #pragma unroll
                for (int j = 0; j < 8; ++j)
                    bacc[j] += qq[b2] * kk[(j - b2) & 7];
            }
        }
    }
    __syncthreads();

    // write Phase-B output to qsm (q dead) for the LN reduction
    *(float4*)(qsm + c * 68 + row * 8)     = make_float4(bacc[0], bacc[1], bacc[2], bacc[3]);
    *(float4*)(qsm + c * 68 + row * 8 + 4) = make_float4(bacc[4], bacc[5], bacc[6], bacc[7]);
    __syncthreads();

    // ---- LayerNorm stats over 128 channels per pixel ----
    {
        float s = 0.f, ss = 0.f;
        #pragma unroll
        for (int u = 0; u < 8; ++u) {
            float v = qsm[(clg * 8 + u) * 68 + p8];
            s += v; ss += v * v;
        }
        ps[clg * 66 + p8] = s;
        pq[clg * 66 + p8] = ss;
    }
    __syncthreads();
    if (t < 64) {
        float sm = 0.f, sq = 0.f;
        #pragma unroll
        for (int g = 0; g < 16; ++g) { sm += ps[g * 66 + t]; sq += pq[g * 66 + t]; }
        float mu  = sm * (1.f / 128.f);
        float var = sq * (1.f / 128.f) - mu * mu;
        mean_s[t] = mu;
        rstd_s[t] = rsqrtf(var + 1e-5f);
    }
    __syncthreads();

    // ---- normalize, scale/shift, multiply by v -> ksm (k dead) ----
    {
        float lw = __ldg(&ln_w[c]);
        float lb = __ldg(&ln_b[c]);
        float4 v0 = *(const float4*)(vsm + c * 68 + row * 8);
        float4 v1 = *(const float4*)(vsm + c * 68 + row * 8 + 4);
        float vv[8] = {v0.x, v0.y, v0.z, v0.w, v1.x, v1.y, v1.z, v1.w};
        float ov[8];
        #pragma unroll
        for (int j = 0; j < 8; ++j) {
            int px = row * 8 + j;
            float o = (bacc[j] - mean_s[px]) * rstd_s[px] * lw + lb;
            ov[j] = vv[j] * o;
        }
        *(float4*)(ksm + c * 68 + row * 8)     = make_float4(ov[0], ov[1], ov[2], ov[3]);
        *(float4*)(ksm + c * 68 + row * 8 + 4) = make_float4(ov[4], ov[5], ov[6], ov[7]);
    }
    __syncthreads();

    // ---- 1x1 projection 128 -> 64 ----
    {
        float r[4];
        #pragma unroll
        for (int j = 0; j < 4; ++j) r[j] = __ldg(&b_proj[clg * 4 + j]);

        #pragma unroll 8
        for (int cc = 0; cc < 128; ++cc) {
            float ov = ksm[cc * 68 + p8];
            float4 wv = *(const float4*)(wpT + cc * 68 + clg * 4);
            r[0] += ov * wv.x;  r[1] += ov * wv.y;
            r[2] += ov * wv.z;  r[3] += ov * wv.w;
        }

        const int gy = by * 8 + i8;
        const int gx = bx * 8 + j8;
        #pragma unroll
        for (int j = 0; j < 4; ++j) {
            int o = clg * 4 + j;
            out[((size_t)(bb * 64 + o) * IMH + gy) * IMW + gx] = r[j];
        }
    }
}

extern "C" void kernel_launch(void* const* d_in, const int* in_sizes, int n_in,
                              void* d_out, int out_size) {
    const float* x        = (const float*)d_in[0];
    const float* w_hidden = (const float*)d_in[1];
    const float* b_hidden = (const float*)d_in[2];
    const float* w_dw     = (const float*)d_in[3];
    const float* b_dw     = (const float*)d_in[4];
    const float* w_proj   = (const float*)d_in[5];
    const float* b_proj   = (const float*)d_in[6];
    const float* ln_w     = (const float*)d_in[7];
    const float* ln_b     = (const float*)d_in[8];
    float* out = (float*)d_out;

    const int k1_smem = K1_SMEM * sizeof(float);   // 66560 B
    const int k2_smem = K2_SMEM * sizeof(float);   // 174848 B
    cudaFuncSetAttribute(k1_conv1x1, cudaFuncAttributeMaxDynamicSharedMemorySize, k1_smem);
    cudaFuncSetAttribute(k2_rest,    cudaFuncAttributeMaxDynamicSharedMemorySize, k2_smem);

    dim3 g1(512, 4);
    k1_conv1x1<<<g1, 1024, k1_smem>>>(x, w_hidden, b_hidden);

    dim3 g2(32, 32, 4);
    k2_rest<<<g2, 1024, k2_smem>>>(w_dw, b_dw, w_proj, b_proj, ln_w, ln_b, out);
}

// round 9
// speedup vs baseline: 1.4366x; 1.4366x over previous
#include <cuda_runtime.h>
#include <cstdint>

#define IMH 256
#define IMW 256

// 402 MB scratch for hidden = conv1x1(x) + b_hidden, NCHW [4][384][256][256]
__device__ float g_hidden[4 * 384 * 256 * 256];

// ======================= K1: 1x1 conv, whole image, no halo =======================
// grid (512, 4): 512 strips of 128 contiguous pixels per batch. 1024 threads, 2 CTAs/SM.
#define K1_SMEM (64 * 128 + 64 * 132)   // xs + ws = 16640 floats = 66560 B

extern __shared__ float smem[];

__global__ __launch_bounds__(1024, 2)
void k1_conv1x1(const float* __restrict__ x,
                const float* __restrict__ w_hidden,
                const float* __restrict__ b_hidden)
{
    float* xs = smem;              // [64][128]
    float* ws = smem + 64 * 128;   // [64][132]

    const int t   = threadIdx.x;
    const int b   = blockIdx.y;
    const int px0 = blockIdx.x * 128;
    const int w   = t >> 5;        // warp: pixels w*4..w*4+3
    const int l   = t & 31;        // lane: channels l*4..l*4+3

    // stage x strip: xs[c][p] (coalesced)
    for (int idx = t; idx < 64 * 128; idx += 1024) {
        int c = idx >> 7, p = idx & 127;
        xs[idx] = x[((size_t)(b * 64 + c) << 16) + px0 + p];
    }

    for (int pass = 0; pass < 3; ++pass) {
        const int pch = pass * 128;
        __syncthreads();
        for (int idx = t; idx < 64 * 128; idx += 1024) {
            int i = idx & 63, c = idx >> 6;
            ws[i * 132 + c] = w_hidden[(pch + c) * 64 + i];
        }
        __syncthreads();

        float acc[4][4];
        #pragma unroll
        for (int j = 0; j < 4; ++j) {
            float bv = __ldg(&b_hidden[pch + l * 4 + j]);
            acc[j][0] = bv; acc[j][1] = bv; acc[j][2] = bv; acc[j][3] = bv;
        }
        const float* xsp = xs + w * 4;
        const float* wsp = ws + l * 4;
        #pragma unroll 4
        for (int i = 0; i < 64; ++i) {
            float4 xv = *(const float4*)(xsp + i * 128);
            float4 wv = *(const float4*)(wsp + i * 132);
            acc[0][0] += wv.x * xv.x; acc[0][1] += wv.x * xv.y;
            acc[0][2] += wv.x * xv.z; acc[0][3] += wv.x * xv.w;
            acc[1][0] += wv.y * xv.x; acc[1][1] += wv.y * xv.y;
            acc[1][2] += wv.y * xv.z; acc[1][3] += wv.y * xv.w;
            acc[2][0] += wv.z * xv.x; acc[2][1] += wv.z * xv.y;
            acc[2][2] += wv.z * xv.z; acc[2][3] += wv.z * xv.w;
            acc[3][0] += wv.w * xv.x; acc[3][1] += wv.w * xv.y;
            acc[3][2] += wv.w * xv.z; acc[3][3] += wv.w * xv.w;
        }

        #pragma unroll
        for (int j = 0; j < 4; ++j) {
            int c = pch + l * 4 + j;
            float4 hv = make_float4(acc[j][0], acc[j][1], acc[j][2], acc[j][3]);
            *(float4*)(g_hidden + ((size_t)(b * 384 + c) << 16) + px0 + w * 4) = hv;
        }
    }
}

// ======================= K2: dw conv + circ-conv + LN + proj =======================
// grid (32, 32, 4): one 8x8 patch per block. 1024 threads.
#define OFF_HS   0          // hs [128][120] = 15360; wpT[128][68] overlays after passes
#define OFF_WPT  0
#define OFF_Q    15360      // [128][68]
#define OFF_K    24064      // [128][68]
#define OFF_V    32768      // [128][68]
#define OFF_PS   41472      // [16][66]
#define OFF_PQ   42528      // [16][66]
#define OFF_MEAN 43584      // [64]
#define OFF_RSTD 43648      // [64]
#define K2_SMEM  43712      // 174848 bytes

__global__ __launch_bounds__(1024, 1)
void k2_rest(const float* __restrict__ w_dw,
             const float* __restrict__ b_dw,
             const float* __restrict__ w_proj,
             const float* __restrict__ b_proj,
             const float* __restrict__ ln_w,
             const float* __restrict__ ln_b,
             float* __restrict__ out)
{
    float* hs   = smem + OFF_HS;
    float* wpT  = smem + OFF_WPT;
    float* qsm  = smem + OFF_Q;
    float* ksm  = smem + OFF_K;
    float* vsm  = smem + OFF_V;
    float* ps   = smem + OFF_PS;
    float* pq   = smem + OFF_PQ;
    float* mean_s = smem + OFF_MEAN;
    float* rstd_s = smem + OFF_RSTD;

    const int t  = threadIdx.x;
    const int bx = blockIdx.x;
    const int by = blockIdx.y;
    const int bb = blockIdx.z;
    const int gx0 = bx * 8 - 1;
    const int gy0 = by * 8 - 1;

    const int c   = t >> 3;       // 0..127 (dw / B / LN-apply channel)
    const int row = t & 7;        // 0..7
    const int p8  = t & 63;
    const int i8  = p8 >> 3;
    const int j8  = p8 & 7;
    const int clg = t >> 6;       // 0..15

    // ---- staging geometry: tp = t&127 is the SAME tile pixel for all 16 of
    // this thread's loads (1024 stride ≡ 0 mod 128); channels cc0 + 8u.
    const int tp  = t & 127;
    const int cc0 = t >> 7;       // 0..7
    int sty = tp / 10, stx = tp - sty * 10;
    const int sgy = gy0 + sty, sgx = gx0 + stx;
    const bool sload = (tp < 100) && ((unsigned)sgy < IMH) && ((unsigned)sgx < IMW);
    const bool sstore = (tp < 100);
    const size_t gpix = ((size_t)sgy << 8) + sgx;
    const int hoff = sty * 12 + stx;

    // ---- 3 passes: stage hidden tile (zero halo, MLP=16) + depthwise 3x3 ----
    for (int pass = 0; pass < 3; ++pass) {
        const int pch = pass * 128;

        // batched independent loads (front-issued -> MLP=16)
        float v[16];
        const float* gbase = g_hidden + (((size_t)(bb * 384 + pch + cc0)) << 16) + gpix;
        #pragma unroll
        for (int u = 0; u < 16; ++u)
            v[u] = sload ? __ldg(gbase + ((size_t)(8 * u) << 16)) : 0.f;

        __syncthreads();   // hs free (prev dw done)
        if (sstore) {
            #pragma unroll
            for (int u = 0; u < 16; ++u)
                hs[(cc0 + 8 * u) * 120 + hoff] = v[u];
        }
        __syncthreads();

        float* dst = (pass == 0) ? qsm : (pass == 1) ? ksm : vsm;
        float wd9[9];
        #pragma unroll
        for (int tap = 0; tap < 9; ++tap) wd9[tap] = __ldg(&w_dw[(pch + c) * 9 + tap]);
        float bv = __ldg(&b_dw[pch + c]);
        float o8[8];
        #pragma unroll
        for (int j = 0; j < 8; ++j) o8[j] = bv;
        const float* hrow = hs + c * 120 + row * 12;
        #pragma unroll
        for (int dy = 0; dy < 3; ++dy) {
            float4 A0 = *(const float4*)(hrow + dy * 12);
            float4 A1 = *(const float4*)(hrow + dy * 12 + 4);
            float4 A2 = *(const float4*)(hrow + dy * 12 + 8);
            float rr[12] = {A0.x, A0.y, A0.z, A0.w, A1.x, A1.y, A1.z, A1.w,
                            A2.x, A2.y, A2.z, A2.w};
            float w0 = wd9[dy * 3], w1 = wd9[dy * 3 + 1], w2 = wd9[dy * 3 + 2];
            #pragma unroll
            for (int j = 0; j < 8; ++j)
                o8[j] += rr[j] * w0 + rr[j + 1] * w1 + rr[j + 2] * w2;
        }
        *(float4*)(dst + c * 68 + row * 8)     = make_float4(o8[0], o8[1], o8[2], o8[3]);
        *(float4*)(dst + c * 68 + row * 8 + 4) = make_float4(o8[4], o8[5], o8[6], o8[7]);
    }
    __syncthreads();   // dw done with hs -> overlay wpT

    // stage wpT[c][68] = w_proj[o][c]
    for (int idx = t; idx < 64 * 128; idx += 1024) {
        int cc = idx & 127, o = idx >> 7;
        wpT[cc * 68 + o] = w_proj[o * 128 + cc];
    }
    // ordered before proj by the syncs below

    // ---- Phase B: circular conv per 8x8 patch ----
    float bacc[8];
    #pragma unroll
    for (int j = 0; j < 8; ++j) bacc[j] = 0.f;
    {
        const float* qrow = qsm + c * 68;
        const float* krow = ksm + c * 68;
        #pragma unroll
        for (int a = 0; a < 8; ++a) {
            float4 qa = *(const float4*)(qrow + a * 8);
            float4 qb = *(const float4*)(qrow + a * 8 + 4);
            float qq[8] = {qa.x, qa.y, qa.z, qa.w, qb.x, qb.y, qb.z, qb.w};
            int r0 = (row - a) & 7;
            float4 k0 = *(const float4*)(krow + r0 * 8);
            float4 k1 = *(const float4*)(krow + r0 * 8 + 4);
            float kk[8] = {k0.x, k0.y, k0.z, k0.w, k1.x, k1.y, k1.z, k1.w};
            #pragma unroll
            for (int b2 = 0; b2 < 8; ++b2) {
                #pragma unroll
                for (int j = 0; j < 8; ++j)
                    bacc[j] += qq[b2] * kk[(j - b2) & 7];
            }
        }
    }
    __syncthreads();

    // write Phase-B output to qsm (q dead) for the LN reduction
    *(float4*)(qsm + c * 68 + row * 8)     = make_float4(bacc[0], bacc[1], bacc[2], bacc[3]);
    *(float4*)(qsm + c * 68 + row * 8 + 4) = make_float4(bacc[4], bacc[5], bacc[6], bacc[7]);
    __syncthreads();

    // ---- LayerNorm stats over 128 channels per pixel ----
    {
        float s = 0.f, ss = 0.f;
        #pragma unroll
        for (int u = 0; u < 8; ++u) {
            float v2 = qsm[(clg * 8 + u) * 68 + p8];
            s += v2; ss += v2 * v2;
        }
        ps[clg * 66 + p8] = s;
        pq[clg * 66 + p8] = ss;
    }
    __syncthreads();
    if (t < 64) {
        float sm = 0.f, sq = 0.f;
        #pragma unroll
        for (int g = 0; g < 16; ++g) { sm += ps[g * 66 + t]; sq += pq[g * 66 + t]; }
        float mu  = sm * (1.f / 128.f);
        float var = sq * (1.f / 128.f) - mu * mu;
        mean_s[t] = mu;
        rstd_s[t] = rsqrtf(var + 1e-5f);
    }
    __syncthreads();

    // ---- normalize, scale/shift, multiply by v -> ksm (k dead) ----
    {
        float lw = __ldg(&ln_w[c]);
        float lb = __ldg(&ln_b[c]);
        float4 v0 = *(const float4*)(vsm + c * 68 + row * 8);
        float4 v1 = *(const float4*)(vsm + c * 68 + row * 8 + 4);
        float vv[8] = {v0.x, v0.y, v0.z, v0.w, v1.x, v1.y, v1.z, v1.w};
        float ov[8];
        #pragma unroll
        for (int j = 0; j < 8; ++j) {
            int px = row * 8 + j;
            float o = (bacc[j] - mean_s[px]) * rstd_s[px] * lw + lb;
            ov[j] = vv[j] * o;
        }
        *(float4*)(ksm + c * 68 + row * 8)     = make_float4(ov[0], ov[1], ov[2], ov[3]);
        *(float4*)(ksm + c * 68 + row * 8 + 4) = make_float4(ov[4], ov[5], ov[6], ov[7]);
    }
    __syncthreads();

    // ---- 1x1 projection 128 -> 64 ----
    {
        float r[4];
        #pragma unroll
        for (int j = 0; j < 4; ++j) r[j] = __ldg(&b_proj[clg * 4 + j]);

        #pragma unroll 8
        for (int cc = 0; cc < 128; ++cc) {
            float ov = ksm[cc * 68 + p8];
            float4 wv = *(const float4*)(wpT + cc * 68 + clg * 4);
            r[0] += ov * wv.x;  r[1] += ov * wv.y;
            r[2] += ov * wv.z;  r[3] += ov * wv.w;
        }

        const int gy = by * 8 + i8;
        const int gx = bx * 8 + j8;
        #pragma unroll
        for (int j = 0; j < 4; ++j) {
            int o = clg * 4 + j;
            out[((size_t)(bb * 64 + o) * IMH + gy) * IMW + gx] = r[j];
        }
    }
}

extern "C" void kernel_launch(void* const* d_in, const int* in_sizes, int n_in,
                              void* d_out, int out_size) {
    const float* x        = (const float*)d_in[0];
    const float* w_hidden = (const float*)d_in[1];
    const float* b_hidden = (const float*)d_in[2];
    const float* w_dw     = (const float*)d_in[3];
    const float* b_dw     = (const float*)d_in[4];
    const float* w_proj   = (const float*)d_in[5];
    const float* b_proj   = (const float*)d_in[6];
    const float* ln_w     = (const float*)d_in[7];
    const float* ln_b     = (const float*)d_in[8];
    float* out = (float*)d_out;

    const int k1_smem = K1_SMEM * sizeof(float);   // 66560 B
    const int k2_smem = K2_SMEM * sizeof(float);   // 174848 B
    cudaFuncSetAttribute(k1_conv1x1, cudaFuncAttributeMaxDynamicSharedMemorySize, k1_smem);
    cudaFuncSetAttribute(k2_rest,    cudaFuncAttributeMaxDynamicSharedMemorySize, k2_smem);

    dim3 g1(512, 4);
    k1_conv1x1<<<g1, 1024, k1_smem>>>(x, w_hidden, b_hidden);

    dim3 g2(32, 32, 4);
    k2_rest<<<g2, 1024, k2_smem>>>(w_dw, b_dw, w_proj, b_proj, ln_w, ln_b, out);
}